// round 3
// baseline (speedup 1.0000x reference)
#include <cuda_runtime.h>
#include <math.h>

#define TT     4096      // total tokens B*S
#define SEQ    1024
#define BATCH  4
#define HID    4096
#define NH     32
#define NKV    8
#define HD     128
#define QKVN   6144      // NH*HD + 2*NKV*HD
#define NSLOTS 8192
#define ROT    64

// Scratch (no cudaMalloc allowed): qkv activations + attention context
__device__ float g_qkv[(size_t)TT * QKVN];   // ~100.7 MB
__device__ float g_ctx[(size_t)TT * HID];    // ~67 MB

// ---------------------------------------------------------------------------
// SGEMM:  C[M,N] = A[M,K] @ B[N,K]^T   (both operands K-major / row-major)
// Classic 128x128x8 blocktile, 256 threads, 8x8 per-thread microtile.
// A may be one of the device globals; selected by host-passed pointer.
// ---------------------------------------------------------------------------
__global__ __launch_bounds__(256, 2)
void sgemm_tn(const float* __restrict__ A, const float* __restrict__ B,
              float* __restrict__ C, int M, int N, int K) {
    __shared__ float As[8][128];
    __shared__ float Bs[8][128];
    const int bm = blockIdx.y * 128;
    const int bn = blockIdx.x * 128;
    const int tid = threadIdx.x;
    const int lr = tid >> 1;           // 0..127 tile row for loading
    const int lc = (tid & 1) * 4;      // 0 or 4 (k offset)
    const int tm = (tid >> 4) * 8;     // microtile row base
    const int tn = (tid & 15) * 8;     // microtile col base

    float acc[8][8] = {};
    const float* Ap = A + (size_t)(bm + lr) * K + lc;
    const float* Bp = B + (size_t)(bn + lr) * K + lc;

    for (int k0 = 0; k0 < K; k0 += 8) {
        float4 a4 = *(const float4*)(Ap + k0);
        float4 b4 = *(const float4*)(Bp + k0);
        As[lc + 0][lr] = a4.x; As[lc + 1][lr] = a4.y;
        As[lc + 2][lr] = a4.z; As[lc + 3][lr] = a4.w;
        Bs[lc + 0][lr] = b4.x; Bs[lc + 1][lr] = b4.y;
        Bs[lc + 2][lr] = b4.z; Bs[lc + 3][lr] = b4.w;
        __syncthreads();
        #pragma unroll
        for (int kk = 0; kk < 8; kk++) {
            float ra[8], rb[8];
            #pragma unroll
            for (int i = 0; i < 8; i++) ra[i] = As[kk][tm + i];
            #pragma unroll
            for (int j = 0; j < 8; j++) rb[j] = Bs[kk][tn + j];
            #pragma unroll
            for (int i = 0; i < 8; i++)
                #pragma unroll
                for (int j = 0; j < 8; j++)
                    acc[i][j] += ra[i] * rb[j];
        }
        __syncthreads();
    }
    #pragma unroll
    for (int i = 0; i < 8; i++) {
        float4* cp = (float4*)(C + (size_t)(bm + tm + i) * N + bn + tn);
        cp[0] = make_float4(acc[i][0], acc[i][1], acc[i][2], acc[i][3]);
        cp[1] = make_float4(acc[i][4], acc[i][5], acc[i][6], acc[i][7]);
    }
}

// QKV projection: writes into g_qkv (referenced directly, no host symbol query)
__global__ __launch_bounds__(256, 2)
void sgemm_qkv(const float* __restrict__ A, const float* __restrict__ B) {
    __shared__ float As[8][128];
    __shared__ float Bs[8][128];
    const int K = HID, N = QKVN;
    const int bm = blockIdx.y * 128;
    const int bn = blockIdx.x * 128;
    const int tid = threadIdx.x;
    const int lr = tid >> 1;
    const int lc = (tid & 1) * 4;
    const int tm = (tid >> 4) * 8;
    const int tn = (tid & 15) * 8;

    float acc[8][8] = {};
    const float* Ap = A + (size_t)(bm + lr) * K + lc;
    const float* Bp = B + (size_t)(bn + lr) * K + lc;

    for (int k0 = 0; k0 < K; k0 += 8) {
        float4 a4 = *(const float4*)(Ap + k0);
        float4 b4 = *(const float4*)(Bp + k0);
        As[lc + 0][lr] = a4.x; As[lc + 1][lr] = a4.y;
        As[lc + 2][lr] = a4.z; As[lc + 3][lr] = a4.w;
        Bs[lc + 0][lr] = b4.x; Bs[lc + 1][lr] = b4.y;
        Bs[lc + 2][lr] = b4.z; Bs[lc + 3][lr] = b4.w;
        __syncthreads();
        #pragma unroll
        for (int kk = 0; kk < 8; kk++) {
            float ra[8], rb[8];
            #pragma unroll
            for (int i = 0; i < 8; i++) ra[i] = As[kk][tm + i];
            #pragma unroll
            for (int j = 0; j < 8; j++) rb[j] = Bs[kk][tn + j];
            #pragma unroll
            for (int i = 0; i < 8; i++)
                #pragma unroll
                for (int j = 0; j < 8; j++)
                    acc[i][j] += ra[i] * rb[j];
        }
        __syncthreads();
    }
    #pragma unroll
    for (int i = 0; i < 8; i++) {
        float4* cp = (float4*)(g_qkv + (size_t)(bm + tm + i) * N + bn + tn);
        cp[0] = make_float4(acc[i][0], acc[i][1], acc[i][2], acc[i][3]);
        cp[1] = make_float4(acc[i][4], acc[i][5], acc[i][6], acc[i][7]);
    }
}

// O projection: reads g_ctx directly, writes to d_out
__global__ __launch_bounds__(256, 2)
void sgemm_oproj(const float* __restrict__ B, float* __restrict__ C) {
    __shared__ float As[8][128];
    __shared__ float Bs[8][128];
    const int K = HID, N = HID;
    const int bm = blockIdx.y * 128;
    const int bn = blockIdx.x * 128;
    const int tid = threadIdx.x;
    const int lr = tid >> 1;
    const int lc = (tid & 1) * 4;
    const int tm = (tid >> 4) * 8;
    const int tn = (tid & 15) * 8;

    float acc[8][8] = {};
    const float* Ap = g_ctx + (size_t)(bm + lr) * K + lc;
    const float* Bp = B + (size_t)(bn + lr) * K + lc;

    for (int k0 = 0; k0 < K; k0 += 8) {
        float4 a4 = *(const float4*)(Ap + k0);
        float4 b4 = *(const float4*)(Bp + k0);
        As[lc + 0][lr] = a4.x; As[lc + 1][lr] = a4.y;
        As[lc + 2][lr] = a4.z; As[lc + 3][lr] = a4.w;
        Bs[lc + 0][lr] = b4.x; Bs[lc + 1][lr] = b4.y;
        Bs[lc + 2][lr] = b4.z; Bs[lc + 3][lr] = b4.w;
        __syncthreads();
        #pragma unroll
        for (int kk = 0; kk < 8; kk++) {
            float ra[8], rb[8];
            #pragma unroll
            for (int i = 0; i < 8; i++) ra[i] = As[kk][tm + i];
            #pragma unroll
            for (int j = 0; j < 8; j++) rb[j] = Bs[kk][tn + j];
            #pragma unroll
            for (int i = 0; i < 8; i++)
                #pragma unroll
                for (int j = 0; j < 8; j++)
                    acc[i][j] += ra[i] * rb[j];
        }
        __syncthreads();
    }
    #pragma unroll
    for (int i = 0; i < 8; i++) {
        float4* cp = (float4*)(C + (size_t)(bm + tm + i) * N + bn + tn);
        cp[0] = make_float4(acc[i][0], acc[i][1], acc[i][2], acc[i][3]);
        cp[1] = make_float4(acc[i][4], acc[i][5], acc[i][6], acc[i][7]);
    }
}

// ---------------------------------------------------------------------------
// Copy input caches into output caches (slots not written keep input values).
// ---------------------------------------------------------------------------
__global__ void copy_caches(const float4* __restrict__ kc, const float4* __restrict__ vc,
                            float4* __restrict__ okc, float4* __restrict__ ovc, int n4) {
    int i = blockIdx.x * blockDim.x + threadIdx.x;
    if (i < n4) { okc[i] = kc[i]; ovc[i] = vc[i]; }
}

// ---------------------------------------------------------------------------
// RoPE in-place on q and k inside g_qkv; roped k also scattered to key cache.
// ---------------------------------------------------------------------------
__global__ void rope_scatter(const float* __restrict__ cosb,
                             const float* __restrict__ sinb, const int* __restrict__ slots,
                             float* __restrict__ okc) {
    int idx = blockIdx.x * blockDim.x + threadIdx.x;
    if (idx >= TT * (NH + NKV) * ROT) return;
    int r    = idx & (ROT - 1);
    int head = (idx >> 6) % (NH + NKV);
    int t    = idx / (ROT * (NH + NKV));
    float c = cosb[t * ROT + r];
    float s = sinb[t * ROT + r];
    float* base = g_qkv + (size_t)t * QKVN + head * HD;   // q heads 0..31, k heads 32..39
    float x1 = base[r];
    float x2 = base[r + ROT];
    float o1 = x1 * c - x2 * s;
    float o2 = x1 * s + x2 * c;
    base[r] = o1;
    base[r + ROT] = o2;
    if (head >= NH && okc != nullptr) {
        int kvh = head - NH;
        float* kcp = okc + (size_t)slots[t] * (NKV * HD) + kvh * HD;
        kcp[r] = o1;
        kcp[r + ROT] = o2;
    }
}

// v (no rope) -> value cache
__global__ void v_scatter(const int* __restrict__ slots, float* __restrict__ ovc) {
    int idx = blockIdx.x * blockDim.x + threadIdx.x;
    if (idx >= TT * NKV * HD) return;
    int d   = idx & (HD - 1);
    int kvh = (idx >> 7) & (NKV - 1);
    int t   = idx >> 10;
    ovc[(size_t)slots[t] * (NKV * HD) + kvh * HD + d] =
        g_qkv[(size_t)t * QKVN + (NH + NKV) * HD + kvh * HD + d];
}

// ---------------------------------------------------------------------------
// Flash-style causal attention. 64 q-rows per block, stream 64-row K/V tiles.
// 256 threads: tr = tid>>3 owns 2 q-rows; tc = tid&7 owns 8 score cols and a
// 16-wide d-slice of O. Online softmax, row stats reduced over the 8 tc lanes.
// ---------------------------------------------------------------------------
#define ATT_SMEM (3 * 64 * 33 * 16 + 64 * 68 * 4)   // Qs,Ks,Vs (float4, pad) + Ps

__global__ __launch_bounds__(256, 1)
void attn_kernel() {
    extern __shared__ float smraw[];
    float4* Qs = (float4*)smraw;           // [64][33]
    float4* Ks = Qs + 64 * 33;             // [64][33]
    float4* Vs = Ks + 64 * 33;             // [64][33]
    float*  Ps = (float*)(Vs + 64 * 33);   // [64][68]

    const int qt  = blockIdx.x;
    const int h   = blockIdx.y;
    const int b   = blockIdx.z;
    const int kvh = h >> 2;                // H/KVH = 4 groups
    const int tid = threadIdx.x;
    const int tr  = tid >> 3;              // 0..31
    const int tc  = tid & 7;               // 0..7
    const int row0 = tr * 2;
    const float scale = 0.08838834764831845f;   // 1/sqrt(128)

    // Load Q tile (64 x 128)
    const float* qbase = g_qkv + (size_t)(b * SEQ + qt * 64) * QKVN + h * HD;
    for (int i = tid; i < 64 * 32; i += 256) {
        int r = i >> 5, c = i & 31;
        Qs[r * 33 + c] = *(const float4*)(qbase + (size_t)r * QKVN + c * 4);
    }

    float m0 = -INFINITY, m1 = -INFINITY, l0 = 0.f, l1 = 0.f;
    float4 o0[4] = {}, o1[4] = {};

    const float* kbase = g_qkv + (size_t)(b * SEQ) * QKVN + NH * HD + kvh * HD;
    const float* vbase = kbase + NKV * HD;
    const int grow0 = qt * 64 + row0;

    for (int kt = 0; kt <= qt; kt++) {
        __syncthreads();   // previous iter done with Ks/Vs/Ps (also covers Q load)
        for (int i = tid; i < 64 * 32; i += 256) {
            int r = i >> 5, c = i & 31;
            size_t off = (size_t)(kt * 64 + r) * QKVN + c * 4;
            Ks[r * 33 + c] = *(const float4*)(kbase + off);
            Vs[r * 33 + c] = *(const float4*)(vbase + off);
        }
        __syncthreads();

        // S = Q K^T for this thread's 2x8 microtile
        float s0[8] = {}, s1[8] = {};
        #pragma unroll 4
        for (int dv = 0; dv < 32; dv++) {
            float4 qa = Qs[(row0 + 0) * 33 + dv];
            float4 qb = Qs[(row0 + 1) * 33 + dv];
            #pragma unroll
            for (int j = 0; j < 8; j++) {
                float4 kv = Ks[(tc * 8 + j) * 33 + dv];
                s0[j] += qa.x * kv.x; s0[j] += qa.y * kv.y;
                s0[j] += qa.z * kv.z; s0[j] += qa.w * kv.w;
                s1[j] += qb.x * kv.x; s1[j] += qb.y * kv.y;
                s1[j] += qb.z * kv.z; s1[j] += qb.w * kv.w;
            }
        }

        // scale + causal mask + tile row max
        float tm0 = -INFINITY, tm1 = -INFINITY;
        #pragma unroll
        for (int j = 0; j < 8; j++) {
            int gc = kt * 64 + tc * 8 + j;
            s0[j] = (gc <= grow0    ) ? s0[j] * scale : -INFINITY;
            s1[j] = (gc <= grow0 + 1) ? s1[j] * scale : -INFINITY;
            tm0 = fmaxf(tm0, s0[j]);
            tm1 = fmaxf(tm1, s1[j]);
        }
        #pragma unroll
        for (int off = 1; off < 8; off <<= 1) {
            tm0 = fmaxf(tm0, __shfl_xor_sync(0xffffffffu, tm0, off));
            tm1 = fmaxf(tm1, __shfl_xor_sync(0xffffffffu, tm1, off));
        }
        float mn0 = fmaxf(m0, tm0), mn1 = fmaxf(m1, tm1);
        float sc0 = __expf(m0 - mn0), sc1 = __expf(m1 - mn1);

        float ps0 = 0.f, ps1 = 0.f;
        #pragma unroll
        for (int j = 0; j < 8; j++) {
            float p0 = __expf(s0[j] - mn0);
            float p1 = __expf(s1[j] - mn1);
            ps0 += p0; ps1 += p1;
            Ps[(row0 + 0) * 68 + tc * 8 + j] = p0;
            Ps[(row0 + 1) * 68 + tc * 8 + j] = p1;
        }
        #pragma unroll
        for (int off = 1; off < 8; off <<= 1) {
            ps0 += __shfl_xor_sync(0xffffffffu, ps0, off);
            ps1 += __shfl_xor_sync(0xffffffffu, ps1, off);
        }
        l0 = l0 * sc0 + ps0;
        l1 = l1 * sc1 + ps1;
        m0 = mn0; m1 = mn1;
        #pragma unroll
        for (int i = 0; i < 4; i++) {
            o0[i].x *= sc0; o0[i].y *= sc0; o0[i].z *= sc0; o0[i].w *= sc0;
            o1[i].x *= sc1; o1[i].y *= sc1; o1[i].z *= sc1; o1[i].w *= sc1;
        }
        __syncthreads();   // all Ps written

        // O += P @ V  (this thread: 2 rows x 16 d-cols, d base = tc*16)
        #pragma unroll 4
        for (int j = 0; j < 64; j++) {
            float p0 = Ps[(row0 + 0) * 68 + j];
            float p1 = Ps[(row0 + 1) * 68 + j];
            #pragma unroll
            for (int i = 0; i < 4; i++) {
                float4 v = Vs[j * 33 + tc * 4 + i];
                o0[i].x += p0 * v.x; o0[i].y += p0 * v.y;
                o0[i].z += p0 * v.z; o0[i].w += p0 * v.w;
                o1[i].x += p1 * v.x; o1[i].y += p1 * v.y;
                o1[i].z += p1 * v.z; o1[i].w += p1 * v.w;
            }
        }
    }

    float inv0 = 1.f / l0, inv1 = 1.f / l1;
    float4* c0 = (float4*)(g_ctx + (size_t)(b * SEQ + qt * 64 + row0 + 0) * HID + h * HD + tc * 16);
    float4* c1 = (float4*)(g_ctx + (size_t)(b * SEQ + qt * 64 + row0 + 1) * HID + h * HD + tc * 16);
    #pragma unroll
    for (int i = 0; i < 4; i++) {
        c0[i] = make_float4(o0[i].x * inv0, o0[i].y * inv0, o0[i].z * inv0, o0[i].w * inv0);
        c1[i] = make_float4(o1[i].x * inv1, o1[i].y * inv1, o1[i].z * inv1, o1[i].w * inv1);
    }
}

// ---------------------------------------------------------------------------
extern "C" void kernel_launch(void* const* d_in, const int* in_sizes, int n_in,
                              void* d_out, int out_size) {
    const float* hidden = (const float*)d_in[0];
    const float* cosb   = (const float*)d_in[1];
    const float* sinb   = (const float*)d_in[2];
    const float* wqkv   = (const float*)d_in[3];
    const float* wo     = (const float*)d_in[4];
    const float* kc_in  = (const float*)d_in[5];
    const float* vc_in  = (const float*)d_in[6];
    const int*   slots  = (const int*)d_in[7];
    float* out = (float*)d_out;

    // Output layout: [attn_out | new_key_cache | new_value_cache], guarded by out_size.
    const size_t out_elems   = (size_t)TT * HID;
    const size_t cache_elems = (size_t)NSLOTS * NKV * HD;
    float* okc = nullptr;
    float* ovc = nullptr;
    if ((size_t)out_size >= out_elems + 2 * cache_elems) {
        okc = out + out_elems;
        ovc = okc + cache_elems;
    }

    if (okc) {
        int n4 = (int)(cache_elems / 4);
        copy_caches<<<(n4 + 255) / 256, 256>>>((const float4*)kc_in, (const float4*)vc_in,
                                               (float4*)okc, (float4*)ovc, n4);
    }

    // 1) QKV projection -> g_qkv
    sgemm_qkv<<<dim3(QKVN / 128, TT / 128), 256>>>(hidden, wqkv);

    // 2) RoPE (q,k in-place) + k scatter to key cache
    {
        int n = TT * (NH + NKV) * ROT;
        rope_scatter<<<(n + 255) / 256, 256>>>(cosb, sinb, slots, okc);
    }
    // 3) v scatter to value cache
    if (ovc) {
        int n = TT * NKV * HD;
        v_scatter<<<(n + 255) / 256, 256>>>(slots, ovc);
    }

    // 4) causal attention -> g_ctx
    cudaFuncSetAttribute(attn_kernel, cudaFuncAttributeMaxDynamicSharedMemorySize, ATT_SMEM);
    attn_kernel<<<dim3(SEQ / 64, NH, BATCH), 256, ATT_SMEM>>>();

    // 5) output projection -> d_out
    sgemm_oproj<<<dim3(HID / 128, TT / 128), 256>>>(wo, out);
}

// round 5
// speedup vs baseline: 1.4772x; 1.4772x over previous
#include <cuda_runtime.h>
#include <cuda_bf16.h>
#include <math.h>
#include <stdint.h>

#define TT     4096      // total tokens B*S
#define SEQ    1024
#define BATCH  4
#define HID    4096
#define NH     32
#define NKV    8
#define HD     128
#define QKVN   6144      // NH*HD + 2*NKV*HD
#define NSLOTS 8192
#define ROT    64
#define KTOT   4096      // logical GEMM K (= HID)
#define KP     12288     // expanded K: [seg0 | seg1 | seg2]

// ---------------------------------------------------------------------------
// Scratch (no cudaMalloc allowed)
// ---------------------------------------------------------------------------
__device__ float g_qkv[(size_t)TT * QKVN];               // fp32 qkv activations
__device__ float g_ctx[(size_t)TT * HID];                // fp32 attention context
__device__ __nv_bfloat16 g_aexp    [(size_t)TT   * KP];  // hidden  [hi|lo|hi]
__device__ __nv_bfloat16 g_wqkv_exp[(size_t)QKVN * KP];  // w_qkv   [hi|hi|lo]
__device__ __nv_bfloat16 g_wo_exp  [(size_t)HID  * KP];  // w_o     [hi|hi|lo]
__device__ __nv_bfloat16 g_ctx_exp [(size_t)TT   * KP];  // ctx     [hi|lo|hi]

// ---------------------------------------------------------------------------
// helpers
// ---------------------------------------------------------------------------
__device__ __forceinline__ uint32_t smem_u32(const void* p) {
    uint32_t a;
    asm("{ .reg .u64 t; cvta.to.shared.u64 t, %1; cvt.u32.u64 %0, t; }" : "=r"(a) : "l"(p));
    return a;
}
__device__ __forceinline__ void cp_async16(uint32_t dst, const void* src) {
    asm volatile("cp.async.cg.shared.global [%0], [%1], 16;" :: "r"(dst), "l"(src));
}
__device__ __forceinline__ uint32_t lds32(uint32_t a) {
    uint32_t v;
    asm volatile("ld.shared.b32 %0, [%1];" : "=r"(v) : "r"(a));
    return v;
}
__device__ __forceinline__ void mma16816(float* c, uint32_t a0, uint32_t a1, uint32_t a2,
                                         uint32_t a3, uint32_t b0, uint32_t b1) {
    asm volatile(
        "mma.sync.aligned.m16n8k16.row.col.f32.bf16.bf16.f32 "
        "{%0,%1,%2,%3}, {%4,%5,%6,%7}, {%8,%9}, {%0,%1,%2,%3};"
        : "+f"(c[0]), "+f"(c[1]), "+f"(c[2]), "+f"(c[3])
        : "r"(a0), "r"(a1), "r"(a2), "r"(a3), "r"(b0), "r"(b1));
}

// ---------------------------------------------------------------------------
// fp32 -> triple-segment bf16 expansion.
// A-type rows (activations): [hi | lo | hi]
// B-type rows (weights):     [hi | hi | lo]
// mode: 0 hidden->g_aexp(A), 1 wqkv->g_wqkv_exp(B), 2 wo->g_wo_exp(B),
//       3 g_ctx->g_ctx_exp(A)
// ---------------------------------------------------------------------------
__global__ void expand3(const float* __restrict__ src, int rows, int mode) {
    __nv_bfloat16* dst = (mode == 0) ? g_aexp : (mode == 1) ? g_wqkv_exp
                        : (mode == 2) ? g_wo_exp : g_ctx_exp;
    const float* s = (mode == 3) ? g_ctx : src;
    int idx = blockIdx.x * blockDim.x + threadIdx.x;   // one float4 per thread
    int total = rows * (KTOT / 4);
    if (idx >= total) return;
    int row = idx >> 10;               // / 1024
    int c4  = idx & 1023;
    float4 v = *(const float4*)(s + (size_t)row * KTOT + c4 * 4);
    __nv_bfloat16 h0 = __float2bfloat16(v.x);
    __nv_bfloat16 h1 = __float2bfloat16(v.y);
    __nv_bfloat16 h2 = __float2bfloat16(v.z);
    __nv_bfloat16 h3 = __float2bfloat16(v.w);
    __nv_bfloat16 l0 = __float2bfloat16(v.x - __bfloat162float(h0));
    __nv_bfloat16 l1 = __float2bfloat16(v.y - __bfloat162float(h1));
    __nv_bfloat16 l2 = __float2bfloat16(v.z - __bfloat162float(h2));
    __nv_bfloat16 l3 = __float2bfloat16(v.w - __bfloat162float(h3));
    __nv_bfloat162 hA(h0, h1), hB(h2, h3), lA(l0, l1), lB(l2, l3);
    size_t base = (size_t)row * KP + c4 * 4;
    __nv_bfloat162* d0 = (__nv_bfloat162*)(dst + base);              // seg0: hi
    __nv_bfloat162* d1 = (__nv_bfloat162*)(dst + base + KTOT);       // seg1
    __nv_bfloat162* d2 = (__nv_bfloat162*)(dst + base + 2 * KTOT);   // seg2
    d0[0] = hA; d0[1] = hB;
    bool atype = (mode == 0 || mode == 3);
    if (atype) { d1[0] = lA; d1[1] = lB; d2[0] = hA; d2[1] = hB; }
    else       { d1[0] = hA; d1[1] = hB; d2[0] = lA; d2[1] = lB; }
}

// ---------------------------------------------------------------------------
// bf16 mma.sync GEMM: C[M,N] = A'[M,KP] @ B'[N,KP]^T, fp32 accumulate.
// 128x128 CTA tile, BK=32, 3-stage cp.async pipeline, 8 warps (4M x 2N),
// warp tile 32x64 (2 m-frags x 8 n-frags of m16n8k16).
// SMEM rows padded to 40 bf16 (80 B) -> conflict-free b32 fragment loads.
// mode 0: A=g_aexp,   B=g_wqkv_exp, C=g_qkv (N=6144)
// mode 1: A=g_ctx_exp,B=g_wo_exp,   C=outp  (N=4096)
// ---------------------------------------------------------------------------
#define BM 128
#define BN 128
#define BK 32
#define STAGES 3
#define ROWB 80                       // padded row bytes (40 bf16)
#define TILEB (128 * ROWB)            // 10240 per operand tile
#define STAGEB (2 * TILEB)            // 20480
#define GEMM_SMEM (STAGES * STAGEB)   // 61440
#define NCH (KP / BK)                 // 384

__device__ __forceinline__ void load_stage(const __nv_bfloat16* __restrict__ A,
                                           const __nv_bfloat16* __restrict__ B,
                                           int bm, int bn, int k0,
                                           uint32_t stage_base, int tid) {
    #pragma unroll
    for (int it = 0; it < 4; it++) {
        int idx = tid + it * 256;          // 0..1023
        int tile = idx >> 9;               // 0:A 1:B
        int r = (idx >> 2) & 127;
        int c = idx & 3;
        const __nv_bfloat16* src =
            (tile ? (B + (size_t)(bn + r) * KP) : (A + (size_t)(bm + r) * KP)) + k0 + c * 8;
        uint32_t dst = stage_base + tile * TILEB + r * ROWB + c * 16;
        cp_async16(dst, src);
    }
    asm volatile("cp.async.commit_group;" ::: "memory");
}

__global__ __launch_bounds__(256, 2)
void gemm_bf16(int mode, float* __restrict__ outp) {
    extern __shared__ char smem[];
    const uint32_t sb = smem_u32(smem);
    const int tid  = threadIdx.x;
    const int wid  = tid >> 5;
    const int lane = tid & 31;
    const int wm   = wid & 3;          // 0..3, 32 rows each
    const int wn   = wid >> 2;         // 0..1, 64 cols each

    const __nv_bfloat16* A;
    const __nv_bfloat16* B;
    float* C;
    int Ntot;
    if (mode == 0) { A = g_aexp;    B = g_wqkv_exp; C = g_qkv; Ntot = QKVN; }
    else           { A = g_ctx_exp; B = g_wo_exp;   C = outp;  Ntot = HID;  }

    const int bn = blockIdx.x * BN;
    const int bm = blockIdx.y * BM;

    float acc[2][8][4];
    #pragma unroll
    for (int mi = 0; mi < 2; mi++)
        #pragma unroll
        for (int ni = 0; ni < 8; ni++)
            #pragma unroll
            for (int q = 0; q < 4; q++) acc[mi][ni][q] = 0.f;

    // prologue: stages 0 and 1
    load_stage(A, B, bm, bn, 0, sb, tid);
    load_stage(A, B, bm, bn, BK, sb + STAGEB, tid);

    const int arow = wm * 32 + (lane >> 2);
    const int brow = wn * 64 + (lane >> 2);
    const int kb   = (lane & 3) * 4;     // byte offset of this thread's k-pair

    #pragma unroll 1
    for (int i = 0; i < NCH; i++) {
        asm volatile("cp.async.wait_group 1;" ::: "memory");
        __syncthreads();

        const uint32_t As = sb + (i % STAGES) * STAGEB;
        const uint32_t Bs = As + TILEB;

        #pragma unroll
        for (int ks = 0; ks < 2; ks++) {
            const uint32_t koff = ks * 32 + kb;    // bytes within row
            uint32_t a[2][4];
            #pragma unroll
            for (int mi = 0; mi < 2; mi++) {
                uint32_t r0 = As + (arow + mi * 16) * ROWB + koff;
                a[mi][0] = lds32(r0);
                a[mi][1] = lds32(r0 + 8 * ROWB);
                a[mi][2] = lds32(r0 + 16);
                a[mi][3] = lds32(r0 + 8 * ROWB + 16);
            }
            uint32_t b[8][2];
            #pragma unroll
            for (int ni = 0; ni < 8; ni++) {
                uint32_t r0 = Bs + (brow + ni * 8) * ROWB + koff;
                b[ni][0] = lds32(r0);
                b[ni][1] = lds32(r0 + 16);
            }
            #pragma unroll
            for (int mi = 0; mi < 2; mi++)
                #pragma unroll
                for (int ni = 0; ni < 8; ni++)
                    mma16816(acc[mi][ni], a[mi][0], a[mi][1], a[mi][2], a[mi][3],
                             b[ni][0], b[ni][1]);
        }
        __syncthreads();
        if (i + 2 < NCH)
            load_stage(A, B, bm, bn, (i + 2) * BK, sb + ((i + 2) % STAGES) * STAGEB, tid);
    }

    // epilogue: c0,c1 = row, cols n,n+1 ; c2,c3 = row+8
    const int crow = bm + wm * 32 + (lane >> 2);
    const int ccol = bn + wn * 64 + (lane & 3) * 2;
    #pragma unroll
    for (int mi = 0; mi < 2; mi++) {
        #pragma unroll
        for (int ni = 0; ni < 8; ni++) {
            float* p0 = C + (size_t)(crow + mi * 16)     * Ntot + ccol + ni * 8;
            float* p1 = C + (size_t)(crow + mi * 16 + 8) * Ntot + ccol + ni * 8;
            *(float2*)p0 = make_float2(acc[mi][ni][0], acc[mi][ni][1]);
            *(float2*)p1 = make_float2(acc[mi][ni][2], acc[mi][ni][3]);
        }
    }
}

// ---------------------------------------------------------------------------
// Cache copy + RoPE + scatters (unchanged from passing version)
// ---------------------------------------------------------------------------
__global__ void copy_caches(const float4* __restrict__ kc, const float4* __restrict__ vc,
                            float4* __restrict__ okc, float4* __restrict__ ovc, int n4) {
    int i = blockIdx.x * blockDim.x + threadIdx.x;
    if (i < n4) { okc[i] = kc[i]; ovc[i] = vc[i]; }
}

__global__ void rope_scatter(const float* __restrict__ cosb,
                             const float* __restrict__ sinb, const int* __restrict__ slots,
                             float* __restrict__ okc) {
    int idx = blockIdx.x * blockDim.x + threadIdx.x;
    if (idx >= TT * (NH + NKV) * ROT) return;
    int r    = idx & (ROT - 1);
    int head = (idx >> 6) % (NH + NKV);
    int t    = idx / (ROT * (NH + NKV));
    float c = cosb[t * ROT + r];
    float s = sinb[t * ROT + r];
    float* base = g_qkv + (size_t)t * QKVN + head * HD;
    float x1 = base[r];
    float x2 = base[r + ROT];
    float o1 = x1 * c - x2 * s;
    float o2 = x1 * s + x2 * c;
    base[r] = o1;
    base[r + ROT] = o2;
    if (head >= NH && okc != nullptr) {
        int kvh = head - NH;
        float* kcp = okc + (size_t)slots[t] * (NKV * HD) + kvh * HD;
        kcp[r] = o1;
        kcp[r + ROT] = o2;
    }
}

__global__ void v_scatter(const int* __restrict__ slots, float* __restrict__ ovc) {
    int idx = blockIdx.x * blockDim.x + threadIdx.x;
    if (idx >= TT * NKV * HD) return;
    int d   = idx & (HD - 1);
    int kvh = (idx >> 7) & (NKV - 1);
    int t   = idx >> 10;
    ovc[(size_t)slots[t] * (NKV * HD) + kvh * HD + d] =
        g_qkv[(size_t)t * QKVN + (NH + NKV) * HD + kvh * HD + d];
}

// ---------------------------------------------------------------------------
// Flash-style causal attention (fp32, unchanged from passing version)
// ---------------------------------------------------------------------------
#define ATT_SMEM (3 * 64 * 33 * 16 + 64 * 68 * 4)

__global__ __launch_bounds__(256, 1)
void attn_kernel() {
    extern __shared__ float smraw[];
    float4* Qs = (float4*)smraw;
    float4* Ks = Qs + 64 * 33;
    float4* Vs = Ks + 64 * 33;
    float*  Ps = (float*)(Vs + 64 * 33);

    const int qt  = blockIdx.x;
    const int h   = blockIdx.y;
    const int b   = blockIdx.z;
    const int kvh = h >> 2;
    const int tid = threadIdx.x;
    const int tr  = tid >> 3;
    const int tc  = tid & 7;
    const int row0 = tr * 2;
    const float scale = 0.08838834764831845f;

    const float* qbase = g_qkv + (size_t)(b * SEQ + qt * 64) * QKVN + h * HD;
    for (int i = tid; i < 64 * 32; i += 256) {
        int r = i >> 5, c = i & 31;
        Qs[r * 33 + c] = *(const float4*)(qbase + (size_t)r * QKVN + c * 4);
    }

    float m0 = -INFINITY, m1 = -INFINITY, l0 = 0.f, l1 = 0.f;
    float4 o0[4] = {}, o1[4] = {};

    const float* kbase = g_qkv + (size_t)(b * SEQ) * QKVN + NH * HD + kvh * HD;
    const float* vbase = kbase + NKV * HD;
    const int grow0 = qt * 64 + row0;

    for (int kt = 0; kt <= qt; kt++) {
        __syncthreads();
        for (int i = tid; i < 64 * 32; i += 256) {
            int r = i >> 5, c = i & 31;
            size_t off = (size_t)(kt * 64 + r) * QKVN + c * 4;
            Ks[r * 33 + c] = *(const float4*)(kbase + off);
            Vs[r * 33 + c] = *(const float4*)(vbase + off);
        }
        __syncthreads();

        float s0[8] = {}, s1[8] = {};
        #pragma unroll 4
        for (int dv = 0; dv < 32; dv++) {
            float4 qa = Qs[(row0 + 0) * 33 + dv];
            float4 qb = Qs[(row0 + 1) * 33 + dv];
            #pragma unroll
            for (int j = 0; j < 8; j++) {
                float4 kv = Ks[(tc * 8 + j) * 33 + dv];
                s0[j] += qa.x * kv.x; s0[j] += qa.y * kv.y;
                s0[j] += qa.z * kv.z; s0[j] += qa.w * kv.w;
                s1[j] += qb.x * kv.x; s1[j] += qb.y * kv.y;
                s1[j] += qb.z * kv.z; s1[j] += qb.w * kv.w;
            }
        }

        float tm0 = -INFINITY, tm1 = -INFINITY;
        #pragma unroll
        for (int j = 0; j < 8; j++) {
            int gc = kt * 64 + tc * 8 + j;
            s0[j] = (gc <= grow0    ) ? s0[j] * scale : -INFINITY;
            s1[j] = (gc <= grow0 + 1) ? s1[j] * scale : -INFINITY;
            tm0 = fmaxf(tm0, s0[j]);
            tm1 = fmaxf(tm1, s1[j]);
        }
        #pragma unroll
        for (int off = 1; off < 8; off <<= 1) {
            tm0 = fmaxf(tm0, __shfl_xor_sync(0xffffffffu, tm0, off));
            tm1 = fmaxf(tm1, __shfl_xor_sync(0xffffffffu, tm1, off));
        }
        float mn0 = fmaxf(m0, tm0), mn1 = fmaxf(m1, tm1);
        float sc0 = __expf(m0 - mn0), sc1 = __expf(m1 - mn1);

        float ps0 = 0.f, ps1 = 0.f;
        #pragma unroll
        for (int j = 0; j < 8; j++) {
            float p0 = __expf(s0[j] - mn0);
            float p1 = __expf(s1[j] - mn1);
            ps0 += p0; ps1 += p1;
            Ps[(row0 + 0) * 68 + tc * 8 + j] = p0;
            Ps[(row0 + 1) * 68 + tc * 8 + j] = p1;
        }
        #pragma unroll
        for (int off = 1; off < 8; off <<= 1) {
            ps0 += __shfl_xor_sync(0xffffffffu, ps0, off);
            ps1 += __shfl_xor_sync(0xffffffffu, ps1, off);
        }
        l0 = l0 * sc0 + ps0;
        l1 = l1 * sc1 + ps1;
        m0 = mn0; m1 = mn1;
        #pragma unroll
        for (int i = 0; i < 4; i++) {
            o0[i].x *= sc0; o0[i].y *= sc0; o0[i].z *= sc0; o0[i].w *= sc0;
            o1[i].x *= sc1; o1[i].y *= sc1; o1[i].z *= sc1; o1[i].w *= sc1;
        }
        __syncthreads();

        #pragma unroll 4
        for (int j = 0; j < 64; j++) {
            float p0 = Ps[(row0 + 0) * 68 + j];
            float p1 = Ps[(row0 + 1) * 68 + j];
            #pragma unroll
            for (int i = 0; i < 4; i++) {
                float4 v = Vs[j * 33 + tc * 4 + i];
                o0[i].x += p0 * v.x; o0[i].y += p0 * v.y;
                o0[i].z += p0 * v.z; o0[i].w += p0 * v.w;
                o1[i].x += p1 * v.x; o1[i].y += p1 * v.y;
                o1[i].z += p1 * v.z; o1[i].w += p1 * v.w;
            }
        }
    }

    float inv0 = 1.f / l0, inv1 = 1.f / l1;
    float4* c0 = (float4*)(g_ctx + (size_t)(b * SEQ + qt * 64 + row0 + 0) * HID + h * HD + tc * 16);
    float4* c1 = (float4*)(g_ctx + (size_t)(b * SEQ + qt * 64 + row0 + 1) * HID + h * HD + tc * 16);
    #pragma unroll
    for (int i = 0; i < 4; i++) {
        c0[i] = make_float4(o0[i].x * inv0, o0[i].y * inv0, o0[i].z * inv0, o0[i].w * inv0);
        c1[i] = make_float4(o1[i].x * inv1, o1[i].y * inv1, o1[i].z * inv1, o1[i].w * inv1);
    }
}

// ---------------------------------------------------------------------------
extern "C" void kernel_launch(void* const* d_in, const int* in_sizes, int n_in,
                              void* d_out, int out_size) {
    const float* hidden = (const float*)d_in[0];
    const float* cosb   = (const float*)d_in[1];
    const float* sinb   = (const float*)d_in[2];
    const float* wqkv   = (const float*)d_in[3];
    const float* wo     = (const float*)d_in[4];
    const float* kc_in  = (const float*)d_in[5];
    const float* vc_in  = (const float*)d_in[6];
    const int*   slots  = (const int*)d_in[7];
    float* out = (float*)d_out;

    const size_t out_elems   = (size_t)TT * HID;
    const size_t cache_elems = (size_t)NSLOTS * NKV * HD;
    float* okc = nullptr;
    float* ovc = nullptr;
    if ((size_t)out_size >= out_elems + 2 * cache_elems) {
        okc = out + out_elems;
        ovc = okc + cache_elems;
    }

    cudaFuncSetAttribute(gemm_bf16, cudaFuncAttributeMaxDynamicSharedMemorySize, GEMM_SMEM);
    cudaFuncSetAttribute(attn_kernel, cudaFuncAttributeMaxDynamicSharedMemorySize, ATT_SMEM);

    if (okc) {
        int n4 = (int)(cache_elems / 4);
        copy_caches<<<(n4 + 255) / 256, 256>>>((const float4*)kc_in, (const float4*)vc_in,
                                               (float4*)okc, (float4*)ovc, n4);
    }

    // expand operands for QKV GEMM
    expand3<<<(TT   * (KTOT / 4) + 255) / 256, 256>>>(hidden, TT,   0);
    expand3<<<(QKVN * (KTOT / 4) + 255) / 256, 256>>>(wqkv,   QKVN, 1);

    // 1) QKV projection -> g_qkv (HMMA bf16, split-K3)
    gemm_bf16<<<dim3(QKVN / BN, TT / BM), 256, GEMM_SMEM>>>(0, nullptr);

    // 2) RoPE + k scatter
    {
        int n = TT * (NH + NKV) * ROT;
        rope_scatter<<<(n + 255) / 256, 256>>>(cosb, sinb, slots, okc);
    }
    // 3) v scatter
    if (ovc) {
        v_scatter<<<(TT * NKV * HD + 255) / 256, 256>>>(slots, ovc);
    }

    // 4) attention -> g_ctx
    attn_kernel<<<dim3(SEQ / 64, NH, BATCH), 256, ATT_SMEM>>>();

    // 5) expand ctx + w_o, then O projection -> d_out
    expand3<<<(TT  * (KTOT / 4) + 255) / 256, 256>>>(nullptr, TT,  3);
    expand3<<<(HID * (KTOT / 4) + 255) / 256, 256>>>(wo,      HID, 2);
    gemm_bf16<<<dim3(HID / BN, TT / BM), 256, GEMM_SMEM>>>(1, out);
}

// round 6
// speedup vs baseline: 1.5514x; 1.0502x over previous
#include <cuda_runtime.h>
#include <cuda_bf16.h>
#include <math.h>
#include <stdint.h>

#define TT     4096      // total tokens B*S
#define SEQ    1024
#define BATCH  4
#define HID    4096
#define NH     32
#define NKV    8
#define HD     128
#define QKVN   6144      // NH*HD + 2*NKV*HD
#define NSLOTS 8192
#define ROT    64
#define KTOT   4096      // logical GEMM K (= HID)
#define KP     12288     // expanded K: [seg0 | seg1 | seg2]

// ---------------------------------------------------------------------------
// Scratch (no cudaMalloc allowed)
// ---------------------------------------------------------------------------
__device__ float g_qkv[(size_t)TT * QKVN];               // fp32 qkv activations
__device__ float g_ctx[(size_t)TT * HID];                // fp32 attention context
__device__ __nv_bfloat16 g_aexp    [(size_t)TT   * KP];  // hidden  [hi|lo|hi]
__device__ __nv_bfloat16 g_wqkv_exp[(size_t)QKVN * KP];  // w_qkv   [hi|hi|lo]
__device__ __nv_bfloat16 g_wo_exp  [(size_t)HID  * KP];  // w_o     [hi|hi|lo]
__device__ __nv_bfloat16 g_ctx_exp [(size_t)TT   * KP];  // ctx     [hi|lo|hi]

// ---------------------------------------------------------------------------
// helpers
// ---------------------------------------------------------------------------
__device__ __forceinline__ uint32_t smem_u32(const void* p) {
    uint32_t a;
    asm("{ .reg .u64 t; cvta.to.shared.u64 t, %1; cvt.u32.u64 %0, t; }" : "=r"(a) : "l"(p));
    return a;
}
__device__ __forceinline__ void cp_async16(uint32_t dst, const void* src) {
    asm volatile("cp.async.cg.shared.global [%0], [%1], 16;" :: "r"(dst), "l"(src));
}
__device__ __forceinline__ void ldsm4(uint32_t* r, uint32_t addr) {
    asm volatile("ldmatrix.sync.aligned.m8n8.x4.shared.b16 {%0,%1,%2,%3}, [%4];"
        : "=r"(r[0]), "=r"(r[1]), "=r"(r[2]), "=r"(r[3]) : "r"(addr));
}
__device__ __forceinline__ void mma16816(float* c, const uint32_t* a, uint32_t b0, uint32_t b1) {
    asm volatile(
        "mma.sync.aligned.m16n8k16.row.col.f32.bf16.bf16.f32 "
        "{%0,%1,%2,%3}, {%4,%5,%6,%7}, {%8,%9}, {%0,%1,%2,%3};"
        : "+f"(c[0]), "+f"(c[1]), "+f"(c[2]), "+f"(c[3])
        : "r"(a[0]), "r"(a[1]), "r"(a[2]), "r"(a[3]), "r"(b0), "r"(b1));
}

// ---------------------------------------------------------------------------
// fp32 -> triple-segment bf16 expansion.
// A-type rows (activations): [hi | lo | hi]
// B-type rows (weights):     [hi | hi | lo]
// mode: 0 hidden->g_aexp(A), 1 wqkv->g_wqkv_exp(B), 2 wo->g_wo_exp(B),
//       3 g_ctx->g_ctx_exp(A)
// ---------------------------------------------------------------------------
__global__ void expand3(const float* __restrict__ src, int rows, int mode) {
    __nv_bfloat16* dst = (mode == 0) ? g_aexp : (mode == 1) ? g_wqkv_exp
                        : (mode == 2) ? g_wo_exp : g_ctx_exp;
    const float* s = (mode == 3) ? g_ctx : src;
    int idx = blockIdx.x * blockDim.x + threadIdx.x;   // one float4 per thread
    int total = rows * (KTOT / 4);
    if (idx >= total) return;
    int row = idx >> 10;               // / 1024
    int c4  = idx & 1023;
    float4 v = *(const float4*)(s + (size_t)row * KTOT + c4 * 4);
    __nv_bfloat16 h0 = __float2bfloat16(v.x);
    __nv_bfloat16 h1 = __float2bfloat16(v.y);
    __nv_bfloat16 h2 = __float2bfloat16(v.z);
    __nv_bfloat16 h3 = __float2bfloat16(v.w);
    __nv_bfloat16 l0 = __float2bfloat16(v.x - __bfloat162float(h0));
    __nv_bfloat16 l1 = __float2bfloat16(v.y - __bfloat162float(h1));
    __nv_bfloat16 l2 = __float2bfloat16(v.z - __bfloat162float(h2));
    __nv_bfloat16 l3 = __float2bfloat16(v.w - __bfloat162float(h3));
    __nv_bfloat162 hA(h0, h1), hB(h2, h3), lA(l0, l1), lB(l2, l3);
    size_t base = (size_t)row * KP + c4 * 4;
    __nv_bfloat162* d0 = (__nv_bfloat162*)(dst + base);              // seg0: hi
    __nv_bfloat162* d1 = (__nv_bfloat162*)(dst + base + KTOT);       // seg1
    __nv_bfloat162* d2 = (__nv_bfloat162*)(dst + base + 2 * KTOT);   // seg2
    d0[0] = hA; d0[1] = hB;
    bool atype = (mode == 0 || mode == 3);
    if (atype) { d1[0] = lA; d1[1] = lB; d2[0] = hA; d2[1] = hB; }
    else       { d1[0] = hA; d1[1] = hB; d2[0] = lA; d2[1] = lB; }
}

// ---------------------------------------------------------------------------
// bf16 mma.sync GEMM: C[M,N] = A'[M,KP] @ B'[N,KP]^T, fp32 accumulate.
// 128x128 CTA tile, BK=32, 4-stage cp.async pipeline, one sync per BK,
// ldmatrix.x4 fragment loads, 8 warps (4M x 2N), warp tile 32x64.
// SMEM rows padded to 80 B -> conflict-free LDSM (banks 20r mod 32 distinct).
// ---------------------------------------------------------------------------
#define BM 128
#define BN 128
#define BK 32
#define STAGES 4
#define ROWB 80                       // padded row bytes (40 bf16, 64 data)
#define TILEB (128 * ROWB)            // 10240 per operand tile
#define STAGEB (2 * TILEB)            // 20480
#define GEMM_SMEM (STAGES * STAGEB)   // 81920
#define NCH (KP / BK)                 // 384

__device__ __forceinline__ void load_stage(const __nv_bfloat16* __restrict__ A,
                                           const __nv_bfloat16* __restrict__ B,
                                           int bm, int bn, int k0,
                                           uint32_t stage_base, int tid) {
    #pragma unroll
    for (int it = 0; it < 4; it++) {
        int idx = tid + it * 256;          // 0..1023
        int tile = idx >> 9;               // 0:A 1:B
        int r = (idx >> 2) & 127;
        int c = idx & 3;
        const __nv_bfloat16* src =
            (tile ? (B + (size_t)(bn + r) * KP) : (A + (size_t)(bm + r) * KP)) + k0 + c * 8;
        uint32_t dst = stage_base + tile * TILEB + r * ROWB + c * 16;
        cp_async16(dst, src);
    }
    asm volatile("cp.async.commit_group;" ::: "memory");
}

__global__ __launch_bounds__(256, 2)
void gemm_bf16(int mode, float* __restrict__ outp) {
    extern __shared__ char smem[];
    const uint32_t sb = smem_u32(smem);
    const int tid  = threadIdx.x;
    const int wid  = tid >> 5;
    const int lane = tid & 31;
    const int wm   = wid & 3;          // 0..3, 32 rows each
    const int wn   = wid >> 2;         // 0..1, 64 cols each

    const __nv_bfloat16* A;
    const __nv_bfloat16* B;
    float* C;
    int Ntot;
    if (mode == 0) { A = g_aexp;    B = g_wqkv_exp; C = g_qkv; Ntot = QKVN; }
    else           { A = g_ctx_exp; B = g_wo_exp;   C = outp;  Ntot = HID;  }

    const int bn = blockIdx.x * BN;
    const int bm = blockIdx.y * BM;

    float acc[2][8][4];
    #pragma unroll
    for (int mi = 0; mi < 2; mi++)
        #pragma unroll
        for (int ni = 0; ni < 8; ni++)
            #pragma unroll
            for (int q = 0; q < 4; q++) acc[mi][ni][q] = 0.f;

    // LDSM per-thread offsets (within a stage buffer; add stage base + ks*32)
    // A frag (mi): 4 mats: (m..m+7,k0),(m+8..15,k0),(m..m+7,k16B),(m+8..15,k16B)
    const uint32_t a_off0 = (uint32_t)(wm * 32 +      (lane & 15)) * ROWB + (lane >> 4) * 16;
    const uint32_t a_off1 = (uint32_t)(wm * 32 + 16 + (lane & 15)) * ROWB + (lane >> 4) * 16;
    // B frag pair p: mats: (n..n+7,k0),(n..n+7,k16B),(n+8..15,k0),(n+8..15,k16B)
    const uint32_t b_off  = (uint32_t)(wn * 64 + (lane & 7) + ((lane >> 4) & 1) * 8) * ROWB
                          + ((lane >> 3) & 1) * 16;

    // prologue: stages 0,1,2
    load_stage(A, B, bm, bn, 0,      sb,              tid);
    load_stage(A, B, bm, bn, BK,     sb + STAGEB,     tid);
    load_stage(A, B, bm, bn, 2 * BK, sb + 2 * STAGEB, tid);

    #pragma unroll 1
    for (int i = 0; i < NCH; i++) {
        if (i < NCH - 2)      asm volatile("cp.async.wait_group 2;" ::: "memory");
        else if (i == NCH - 2) asm volatile("cp.async.wait_group 1;" ::: "memory");
        else                   asm volatile("cp.async.wait_group 0;" ::: "memory");
        __syncthreads();   // stage i visible to all; all warps done with stage i-1's buffer era

        if (i + 3 < NCH)
            load_stage(A, B, bm, bn, (i + 3) * BK, sb + ((i + 3) & 3) * STAGEB, tid);

        const uint32_t As = sb + (i & 3) * STAGEB;
        const uint32_t Bs = As + TILEB;

        #pragma unroll
        for (int ks = 0; ks < 2; ks++) {
            const uint32_t koff = ks * 32;
            uint32_t a[2][4];
            ldsm4(a[0], As + a_off0 + koff);
            ldsm4(a[1], As + a_off1 + koff);
            uint32_t b[4][4];
            #pragma unroll
            for (int p = 0; p < 4; p++)
                ldsm4(b[p], Bs + b_off + (uint32_t)p * (16 * ROWB) + koff);
            #pragma unroll
            for (int mi = 0; mi < 2; mi++)
                #pragma unroll
                for (int ni = 0; ni < 8; ni++)
                    mma16816(acc[mi][ni], a[mi],
                             b[ni >> 1][(ni & 1) * 2], b[ni >> 1][(ni & 1) * 2 + 1]);
        }
    }

    // epilogue: c0,c1 = row, cols n,n+1 ; c2,c3 = row+8
    const int crow = bm + wm * 32 + (lane >> 2);
    const int ccol = bn + wn * 64 + (lane & 3) * 2;
    #pragma unroll
    for (int mi = 0; mi < 2; mi++) {
        #pragma unroll
        for (int ni = 0; ni < 8; ni++) {
            float* p0 = C + (size_t)(crow + mi * 16)     * Ntot + ccol + ni * 8;
            float* p1 = C + (size_t)(crow + mi * 16 + 8) * Ntot + ccol + ni * 8;
            *(float2*)p0 = make_float2(acc[mi][ni][0], acc[mi][ni][1]);
            *(float2*)p1 = make_float2(acc[mi][ni][2], acc[mi][ni][3]);
        }
    }
}

// ---------------------------------------------------------------------------
// Cache copy + RoPE + scatters (unchanged from passing version)
// ---------------------------------------------------------------------------
__global__ void copy_caches(const float4* __restrict__ kc, const float4* __restrict__ vc,
                            float4* __restrict__ okc, float4* __restrict__ ovc, int n4) {
    int i = blockIdx.x * blockDim.x + threadIdx.x;
    if (i < n4) { okc[i] = kc[i]; ovc[i] = vc[i]; }
}

__global__ void rope_scatter(const float* __restrict__ cosb,
                             const float* __restrict__ sinb, const int* __restrict__ slots,
                             float* __restrict__ okc) {
    int idx = blockIdx.x * blockDim.x + threadIdx.x;
    if (idx >= TT * (NH + NKV) * ROT) return;
    int r    = idx & (ROT - 1);
    int head = (idx >> 6) % (NH + NKV);
    int t    = idx / (ROT * (NH + NKV));
    float c = cosb[t * ROT + r];
    float s = sinb[t * ROT + r];
    float* base = g_qkv + (size_t)t * QKVN + head * HD;
    float x1 = base[r];
    float x2 = base[r + ROT];
    float o1 = x1 * c - x2 * s;
    float o2 = x1 * s + x2 * c;
    base[r] = o1;
    base[r + ROT] = o2;
    if (head >= NH && okc != nullptr) {
        int kvh = head - NH;
        float* kcp = okc + (size_t)slots[t] * (NKV * HD) + kvh * HD;
        kcp[r] = o1;
        kcp[r + ROT] = o2;
    }
}

__global__ void v_scatter(const int* __restrict__ slots, float* __restrict__ ovc) {
    int idx = blockIdx.x * blockDim.x + threadIdx.x;
    if (idx >= TT * NKV * HD) return;
    int d   = idx & (HD - 1);
    int kvh = (idx >> 7) & (NKV - 1);
    int t   = idx >> 10;
    ovc[(size_t)slots[t] * (NKV * HD) + kvh * HD + d] =
        g_qkv[(size_t)t * QKVN + (NH + NKV) * HD + kvh * HD + d];
}

// ---------------------------------------------------------------------------
// Flash-style causal attention (fp32, unchanged from passing version)
// ---------------------------------------------------------------------------
#define ATT_SMEM (3 * 64 * 33 * 16 + 64 * 68 * 4)

__global__ __launch_bounds__(256, 1)
void attn_kernel() {
    extern __shared__ float smraw[];
    float4* Qs = (float4*)smraw;
    float4* Ks = Qs + 64 * 33;
    float4* Vs = Ks + 64 * 33;
    float*  Ps = (float*)(Vs + 64 * 33);

    const int qt  = blockIdx.x;
    const int h   = blockIdx.y;
    const int b   = blockIdx.z;
    const int kvh = h >> 2;
    const int tid = threadIdx.x;
    const int tr  = tid >> 3;
    const int tc  = tid & 7;
    const int row0 = tr * 2;
    const float scale = 0.08838834764831845f;

    const float* qbase = g_qkv + (size_t)(b * SEQ + qt * 64) * QKVN + h * HD;
    for (int i = tid; i < 64 * 32; i += 256) {
        int r = i >> 5, c = i & 31;
        Qs[r * 33 + c] = *(const float4*)(qbase + (size_t)r * QKVN + c * 4);
    }

    float m0 = -INFINITY, m1 = -INFINITY, l0 = 0.f, l1 = 0.f;
    float4 o0[4] = {}, o1[4] = {};

    const float* kbase = g_qkv + (size_t)(b * SEQ) * QKVN + NH * HD + kvh * HD;
    const float* vbase = kbase + NKV * HD;
    const int grow0 = qt * 64 + row0;

    for (int kt = 0; kt <= qt; kt++) {
        __syncthreads();
        for (int i = tid; i < 64 * 32; i += 256) {
            int r = i >> 5, c = i & 31;
            size_t off = (size_t)(kt * 64 + r) * QKVN + c * 4;
            Ks[r * 33 + c] = *(const float4*)(kbase + off);
            Vs[r * 33 + c] = *(const float4*)(vbase + off);
        }
        __syncthreads();

        float s0[8] = {}, s1[8] = {};
        #pragma unroll 4
        for (int dv = 0; dv < 32; dv++) {
            float4 qa = Qs[(row0 + 0) * 33 + dv];
            float4 qb = Qs[(row0 + 1) * 33 + dv];
            #pragma unroll
            for (int j = 0; j < 8; j++) {
                float4 kv = Ks[(tc * 8 + j) * 33 + dv];
                s0[j] += qa.x * kv.x; s0[j] += qa.y * kv.y;
                s0[j] += qa.z * kv.z; s0[j] += qa.w * kv.w;
                s1[j] += qb.x * kv.x; s1[j] += qb.y * kv.y;
                s1[j] += qb.z * kv.z; s1[j] += qb.w * kv.w;
            }
        }

        float tm0 = -INFINITY, tm1 = -INFINITY;
        #pragma unroll
        for (int j = 0; j < 8; j++) {
            int gc = kt * 64 + tc * 8 + j;
            s0[j] = (gc <= grow0    ) ? s0[j] * scale : -INFINITY;
            s1[j] = (gc <= grow0 + 1) ? s1[j] * scale : -INFINITY;
            tm0 = fmaxf(tm0, s0[j]);
            tm1 = fmaxf(tm1, s1[j]);
        }
        #pragma unroll
        for (int off = 1; off < 8; off <<= 1) {
            tm0 = fmaxf(tm0, __shfl_xor_sync(0xffffffffu, tm0, off));
            tm1 = fmaxf(tm1, __shfl_xor_sync(0xffffffffu, tm1, off));
        }
        float mn0 = fmaxf(m0, tm0), mn1 = fmaxf(m1, tm1);
        float sc0 = __expf(m0 - mn0), sc1 = __expf(m1 - mn1);

        float ps0 = 0.f, ps1 = 0.f;
        #pragma unroll
        for (int j = 0; j < 8; j++) {
            float p0 = __expf(s0[j] - mn0);
            float p1 = __expf(s1[j] - mn1);
            ps0 += p0; ps1 += p1;
            Ps[(row0 + 0) * 68 + tc * 8 + j] = p0;
            Ps[(row0 + 1) * 68 + tc * 8 + j] = p1;
        }
        #pragma unroll
        for (int off = 1; off < 8; off <<= 1) {
            ps0 += __shfl_xor_sync(0xffffffffu, ps0, off);
            ps1 += __shfl_xor_sync(0xffffffffu, ps1, off);
        }
        l0 = l0 * sc0 + ps0;
        l1 = l1 * sc1 + ps1;
        m0 = mn0; m1 = mn1;
        #pragma unroll
        for (int i = 0; i < 4; i++) {
            o0[i].x *= sc0; o0[i].y *= sc0; o0[i].z *= sc0; o0[i].w *= sc0;
            o1[i].x *= sc1; o1[i].y *= sc1; o1[i].z *= sc1; o1[i].w *= sc1;
        }
        __syncthreads();

        #pragma unroll 4
        for (int j = 0; j < 64; j++) {
            float p0 = Ps[(row0 + 0) * 68 + j];
            float p1 = Ps[(row0 + 1) * 68 + j];
            #pragma unroll
            for (int i = 0; i < 4; i++) {
                float4 v = Vs[j * 33 + tc * 4 + i];
                o0[i].x += p0 * v.x; o0[i].y += p0 * v.y;
                o0[i].z += p0 * v.z; o0[i].w += p0 * v.w;
                o1[i].x += p1 * v.x; o1[i].y += p1 * v.y;
                o1[i].z += p1 * v.z; o1[i].w += p1 * v.w;
            }
        }
    }

    float inv0 = 1.f / l0, inv1 = 1.f / l1;
    float4* c0 = (float4*)(g_ctx + (size_t)(b * SEQ + qt * 64 + row0 + 0) * HID + h * HD + tc * 16);
    float4* c1 = (float4*)(g_ctx + (size_t)(b * SEQ + qt * 64 + row0 + 1) * HID + h * HD + tc * 16);
    #pragma unroll
    for (int i = 0; i < 4; i++) {
        c0[i] = make_float4(o0[i].x * inv0, o0[i].y * inv0, o0[i].z * inv0, o0[i].w * inv0);
        c1[i] = make_float4(o1[i].x * inv1, o1[i].y * inv1, o1[i].z * inv1, o1[i].w * inv1);
    }
}

// ---------------------------------------------------------------------------
extern "C" void kernel_launch(void* const* d_in, const int* in_sizes, int n_in,
                              void* d_out, int out_size) {
    const float* hidden = (const float*)d_in[0];
    const float* cosb   = (const float*)d_in[1];
    const float* sinb   = (const float*)d_in[2];
    const float* wqkv   = (const float*)d_in[3];
    const float* wo     = (const float*)d_in[4];
    const float* kc_in  = (const float*)d_in[5];
    const float* vc_in  = (const float*)d_in[6];
    const int*   slots  = (const int*)d_in[7];
    float* out = (float*)d_out;

    const size_t out_elems   = (size_t)TT * HID;
    const size_t cache_elems = (size_t)NSLOTS * NKV * HD;
    float* okc = nullptr;
    float* ovc = nullptr;
    if ((size_t)out_size >= out_elems + 2 * cache_elems) {
        okc = out + out_elems;
        ovc = okc + cache_elems;
    }

    cudaFuncSetAttribute(gemm_bf16, cudaFuncAttributeMaxDynamicSharedMemorySize, GEMM_SMEM);
    cudaFuncSetAttribute(attn_kernel, cudaFuncAttributeMaxDynamicSharedMemorySize, ATT_SMEM);

    if (okc) {
        int n4 = (int)(cache_elems / 4);
        copy_caches<<<(n4 + 255) / 256, 256>>>((const float4*)kc_in, (const float4*)vc_in,
                                               (float4*)okc, (float4*)ovc, n4);
    }

    // expand operands for QKV GEMM
    expand3<<<(TT   * (KTOT / 4) + 255) / 256, 256>>>(hidden, TT,   0);
    expand3<<<(QKVN * (KTOT / 4) + 255) / 256, 256>>>(wqkv,   QKVN, 1);

    // 1) QKV projection -> g_qkv (HMMA bf16, split-K3)
    gemm_bf16<<<dim3(QKVN / BN, TT / BM), 256, GEMM_SMEM>>>(0, nullptr);

    // 2) RoPE + k scatter
    {
        int n = TT * (NH + NKV) * ROT;
        rope_scatter<<<(n + 255) / 256, 256>>>(cosb, sinb, slots, okc);
    }
    // 3) v scatter
    if (ovc) {
        v_scatter<<<(TT * NKV * HD + 255) / 256, 256>>>(slots, ovc);
    }

    // 4) attention -> g_ctx
    attn_kernel<<<dim3(SEQ / 64, NH, BATCH), 256, ATT_SMEM>>>();

    // 5) expand ctx + w_o, then O projection -> d_out
    expand3<<<(TT  * (KTOT / 4) + 255) / 256, 256>>>(nullptr, TT,  3);
    expand3<<<(HID * (KTOT / 4) + 255) / 256, 256>>>(wo,      HID, 2);
    gemm_bf16<<<dim3(HID / BN, TT / BM), 256, GEMM_SMEM>>>(1, out);
}

// round 7
// speedup vs baseline: 3.9338x; 2.5357x over previous
#include <cuda_runtime.h>
#include <cuda_bf16.h>
#include <math.h>
#include <stdint.h>

#define TT     4096      // total tokens B*S
#define SEQ    1024
#define BATCH  4
#define HID    4096
#define NH     32
#define NKV    8
#define HD     128
#define QKVN   6144      // NH*HD + 2*NKV*HD
#define NSLOTS 8192
#define ROT    64
#define KTOT   4096      // logical GEMM K (= HID)
#define KP     12288     // expanded K: [seg0 | seg1 | seg2]

// ---------------------------------------------------------------------------
// Scratch (no cudaMalloc allowed)
// ---------------------------------------------------------------------------
__device__ float g_qkv[(size_t)TT * QKVN];               // fp32 qkv activations
__device__ float g_ctx[(size_t)TT * HID];                // fp32 attention context
__device__ __nv_bfloat16 g_aexp    [(size_t)TT   * KP];  // hidden  [hi|lo|hi]
__device__ __nv_bfloat16 g_wqkv_exp[(size_t)QKVN * KP];  // w_qkv   [hi|hi|lo]
__device__ __nv_bfloat16 g_wo_exp  [(size_t)HID  * KP];  // w_o     [hi|hi|lo]
__device__ __nv_bfloat16 g_ctx_exp [(size_t)TT   * KP];  // ctx     [hi|lo|hi]

// ---------------------------------------------------------------------------
// helpers
// ---------------------------------------------------------------------------
__device__ __forceinline__ uint32_t smem_u32(const void* p) {
    uint32_t a;
    asm("{ .reg .u64 t; cvta.to.shared.u64 t, %1; cvt.u32.u64 %0, t; }" : "=r"(a) : "l"(p));
    return a;
}
__device__ __forceinline__ void cp_async16(uint32_t dst, const void* src) {
    asm volatile("cp.async.cg.shared.global [%0], [%1], 16;" :: "r"(dst), "l"(src));
}
__device__ __forceinline__ void ldsm4(uint32_t* r, uint32_t addr) {
    asm volatile("ldmatrix.sync.aligned.m8n8.x4.shared.b16 {%0,%1,%2,%3}, [%4];"
        : "=r"(r[0]), "=r"(r[1]), "=r"(r[2]), "=r"(r[3]) : "r"(addr));
}
__device__ __forceinline__ void ldsm4t(uint32_t* r, uint32_t addr) {
    asm volatile("ldmatrix.sync.aligned.m8n8.x4.trans.shared.b16 {%0,%1,%2,%3}, [%4];"
        : "=r"(r[0]), "=r"(r[1]), "=r"(r[2]), "=r"(r[3]) : "r"(addr));
}
__device__ __forceinline__ void mma16816(float* c, const uint32_t* a, uint32_t b0, uint32_t b1) {
    asm volatile(
        "mma.sync.aligned.m16n8k16.row.col.f32.bf16.bf16.f32 "
        "{%0,%1,%2,%3}, {%4,%5,%6,%7}, {%8,%9}, {%0,%1,%2,%3};"
        : "+f"(c[0]), "+f"(c[1]), "+f"(c[2]), "+f"(c[3])
        : "r"(a[0]), "r"(a[1]), "r"(a[2]), "r"(a[3]), "r"(b0), "r"(b1));
}
__device__ __forceinline__ uint32_t packbf2(float lo, float hi) {
    __nv_bfloat162 v(__float2bfloat16(lo), __float2bfloat16(hi));
    return *(uint32_t*)&v;
}

// ---------------------------------------------------------------------------
// fp32 -> triple-segment bf16 expansion (GEMM operands)
// A-type rows (activations): [hi | lo | hi] ; B-type rows (weights): [hi | hi | lo]
// ---------------------------------------------------------------------------
__global__ void expand3(const float* __restrict__ src, int rows, int mode) {
    __nv_bfloat16* dst = (mode == 0) ? g_aexp : (mode == 1) ? g_wqkv_exp
                        : (mode == 2) ? g_wo_exp : g_ctx_exp;
    const float* s = (mode == 3) ? g_ctx : src;
    int idx = blockIdx.x * blockDim.x + threadIdx.x;
    int total = rows * (KTOT / 4);
    if (idx >= total) return;
    int row = idx >> 10;
    int c4  = idx & 1023;
    float4 v = *(const float4*)(s + (size_t)row * KTOT + c4 * 4);
    __nv_bfloat16 h0 = __float2bfloat16(v.x);
    __nv_bfloat16 h1 = __float2bfloat16(v.y);
    __nv_bfloat16 h2 = __float2bfloat16(v.z);
    __nv_bfloat16 h3 = __float2bfloat16(v.w);
    __nv_bfloat16 l0 = __float2bfloat16(v.x - __bfloat162float(h0));
    __nv_bfloat16 l1 = __float2bfloat16(v.y - __bfloat162float(h1));
    __nv_bfloat16 l2 = __float2bfloat16(v.z - __bfloat162float(h2));
    __nv_bfloat16 l3 = __float2bfloat16(v.w - __bfloat162float(h3));
    __nv_bfloat162 hA(h0, h1), hB(h2, h3), lA(l0, l1), lB(l2, l3);
    size_t base = (size_t)row * KP + c4 * 4;
    __nv_bfloat162* d0 = (__nv_bfloat162*)(dst + base);
    __nv_bfloat162* d1 = (__nv_bfloat162*)(dst + base + KTOT);
    __nv_bfloat162* d2 = (__nv_bfloat162*)(dst + base + 2 * KTOT);
    d0[0] = hA; d0[1] = hB;
    bool atype = (mode == 0 || mode == 3);
    if (atype) { d1[0] = lA; d1[1] = lB; d2[0] = hA; d2[1] = hB; }
    else       { d1[0] = hA; d1[1] = hB; d2[0] = lA; d2[1] = lB; }
}

// ---------------------------------------------------------------------------
// bf16 mma.sync GEMM (unchanged from round 6)
// ---------------------------------------------------------------------------
#define BM 128
#define BN 128
#define BK 32
#define STAGES 4
#define ROWB 80
#define TILEB (128 * ROWB)
#define STAGEB (2 * TILEB)
#define GEMM_SMEM (STAGES * STAGEB)
#define NCH (KP / BK)

__device__ __forceinline__ void load_stage(const __nv_bfloat16* __restrict__ A,
                                           const __nv_bfloat16* __restrict__ B,
                                           int bm, int bn, int k0,
                                           uint32_t stage_base, int tid) {
    #pragma unroll
    for (int it = 0; it < 4; it++) {
        int idx = tid + it * 256;
        int tile = idx >> 9;
        int r = (idx >> 2) & 127;
        int c = idx & 3;
        const __nv_bfloat16* src =
            (tile ? (B + (size_t)(bn + r) * KP) : (A + (size_t)(bm + r) * KP)) + k0 + c * 8;
        uint32_t dst = stage_base + tile * TILEB + r * ROWB + c * 16;
        cp_async16(dst, src);
    }
    asm volatile("cp.async.commit_group;" ::: "memory");
}

__global__ __launch_bounds__(256, 2)
void gemm_bf16(int mode, float* __restrict__ outp) {
    extern __shared__ char smem[];
    const uint32_t sb = smem_u32(smem);
    const int tid  = threadIdx.x;
    const int wid  = tid >> 5;
    const int lane = tid & 31;
    const int wm   = wid & 3;
    const int wn   = wid >> 2;

    const __nv_bfloat16* A;
    const __nv_bfloat16* B;
    float* C;
    int Ntot;
    if (mode == 0) { A = g_aexp;    B = g_wqkv_exp; C = g_qkv; Ntot = QKVN; }
    else           { A = g_ctx_exp; B = g_wo_exp;   C = outp;  Ntot = HID;  }

    const int bn = blockIdx.x * BN;
    const int bm = blockIdx.y * BM;

    float acc[2][8][4];
    #pragma unroll
    for (int mi = 0; mi < 2; mi++)
        #pragma unroll
        for (int ni = 0; ni < 8; ni++)
            #pragma unroll
            for (int q = 0; q < 4; q++) acc[mi][ni][q] = 0.f;

    const uint32_t a_off0 = (uint32_t)(wm * 32 +      (lane & 15)) * ROWB + (lane >> 4) * 16;
    const uint32_t a_off1 = (uint32_t)(wm * 32 + 16 + (lane & 15)) * ROWB + (lane >> 4) * 16;
    const uint32_t b_off  = (uint32_t)(wn * 64 + (lane & 7) + ((lane >> 4) & 1) * 8) * ROWB
                          + ((lane >> 3) & 1) * 16;

    load_stage(A, B, bm, bn, 0,      sb,              tid);
    load_stage(A, B, bm, bn, BK,     sb + STAGEB,     tid);
    load_stage(A, B, bm, bn, 2 * BK, sb + 2 * STAGEB, tid);

    #pragma unroll 1
    for (int i = 0; i < NCH; i++) {
        if (i < NCH - 2)       asm volatile("cp.async.wait_group 2;" ::: "memory");
        else if (i == NCH - 2) asm volatile("cp.async.wait_group 1;" ::: "memory");
        else                   asm volatile("cp.async.wait_group 0;" ::: "memory");
        __syncthreads();

        if (i + 3 < NCH)
            load_stage(A, B, bm, bn, (i + 3) * BK, sb + ((i + 3) & 3) * STAGEB, tid);

        const uint32_t As = sb + (i & 3) * STAGEB;
        const uint32_t Bs = As + TILEB;

        #pragma unroll
        for (int ks = 0; ks < 2; ks++) {
            const uint32_t koff = ks * 32;
            uint32_t a[2][4];
            ldsm4(a[0], As + a_off0 + koff);
            ldsm4(a[1], As + a_off1 + koff);
            uint32_t b[4][4];
            #pragma unroll
            for (int p = 0; p < 4; p++)
                ldsm4(b[p], Bs + b_off + (uint32_t)p * (16 * ROWB) + koff);
            #pragma unroll
            for (int mi = 0; mi < 2; mi++)
                #pragma unroll
                for (int ni = 0; ni < 8; ni++)
                    mma16816(acc[mi][ni], a[mi],
                             b[ni >> 1][(ni & 1) * 2], b[ni >> 1][(ni & 1) * 2 + 1]);
        }
    }

    const int crow = bm + wm * 32 + (lane >> 2);
    const int ccol = bn + wn * 64 + (lane & 3) * 2;
    #pragma unroll
    for (int mi = 0; mi < 2; mi++) {
        #pragma unroll
        for (int ni = 0; ni < 8; ni++) {
            float* p0 = C + (size_t)(crow + mi * 16)     * Ntot + ccol + ni * 8;
            float* p1 = C + (size_t)(crow + mi * 16 + 8) * Ntot + ccol + ni * 8;
            *(float2*)p0 = make_float2(acc[mi][ni][0], acc[mi][ni][1]);
            *(float2*)p1 = make_float2(acc[mi][ni][2], acc[mi][ni][3]);
        }
    }
}

// ---------------------------------------------------------------------------
// Cache copy + RoPE + scatters (unchanged)
// ---------------------------------------------------------------------------
__global__ void copy_caches(const float4* __restrict__ kc, const float4* __restrict__ vc,
                            float4* __restrict__ okc, float4* __restrict__ ovc, int n4) {
    int i = blockIdx.x * blockDim.x + threadIdx.x;
    if (i < n4) { okc[i] = kc[i]; ovc[i] = vc[i]; }
}

__global__ void rope_scatter(const float* __restrict__ cosb,
                             const float* __restrict__ sinb, const int* __restrict__ slots,
                             float* __restrict__ okc) {
    int idx = blockIdx.x * blockDim.x + threadIdx.x;
    if (idx >= TT * (NH + NKV) * ROT) return;
    int r    = idx & (ROT - 1);
    int head = (idx >> 6) % (NH + NKV);
    int t    = idx / (ROT * (NH + NKV));
    float c = cosb[t * ROT + r];
    float s = sinb[t * ROT + r];
    float* base = g_qkv + (size_t)t * QKVN + head * HD;
    float x1 = base[r];
    float x2 = base[r + ROT];
    float o1 = x1 * c - x2 * s;
    float o2 = x1 * s + x2 * c;
    base[r] = o1;
    base[r + ROT] = o2;
    if (head >= NH && okc != nullptr) {
        int kvh = head - NH;
        float* kcp = okc + (size_t)slots[t] * (NKV * HD) + kvh * HD;
        kcp[r] = o1;
        kcp[r + ROT] = o2;
    }
}

__global__ void v_scatter(const int* __restrict__ slots, float* __restrict__ ovc) {
    int idx = blockIdx.x * blockDim.x + threadIdx.x;
    if (idx >= TT * NKV * HD) return;
    int d   = idx & (HD - 1);
    int kvh = (idx >> 7) & (NKV - 1);
    int t   = idx >> 10;
    ovc[(size_t)slots[t] * (NKV * HD) + kvh * HD + d] =
        g_qkv[(size_t)t * QKVN + (NH + NKV) * HD + kvh * HD + d];
}

// ---------------------------------------------------------------------------
// Tensor-core flash attention (bf16 split, fp32 accumulate).
// CTA: 128 q-rows, 8 warps, warp owns 16 rows (softmax warp-local).
// K/V tiles: 64 keys. Smem rows padded to 272 B (conflict-free ldmatrix).
// QK^T: Qh*Kh + Ql*Kh + Qh*Kl. P*V: Ph*Vh + Pl*Vh + Ph*Vl.
// ---------------------------------------------------------------------------
#define ASTR 272                        // padded row bytes (128 bf16 + 8 pad)
#define QH_OFF 0
#define QL_OFF (128 * ASTR)             // 34816
#define KH_OFF (2 * 128 * ASTR)         // 69632
#define KL_OFF (KH_OFF + 64 * ASTR)
#define VH_OFF (KL_OFF + 64 * ASTR)
#define VL_OFF (VH_OFF + 64 * ASTR)
#define ATT_SMEM (VL_OFF + 64 * ASTR)   // 139264

__global__ __launch_bounds__(256, 1)
void attn_mma() {
    extern __shared__ char sm[];
    const uint32_t sb = smem_u32(sm);
    const int qt  = blockIdx.x;          // 0..7 (128-row q tiles)
    const int h   = blockIdx.y;
    const int b   = blockIdx.z;
    const int kvh = h >> 2;
    const int tid  = threadIdx.x;
    const int wid  = tid >> 5;
    const int lane = tid & 31;
    // softmax scale * log2(e), folded into Q
    const float qscale = 0.08838834764831845f * 1.4426950408889634f;

    // ---- load Q tile (128 x 128), scale + hi/lo split ----
    const float* qbase = g_qkv + (size_t)(b * SEQ + qt * 128) * QKVN + h * HD;
    for (int i = tid; i < 128 * 32; i += 256) {
        int r = i >> 5, c = i & 31;
        float4 v = *(const float4*)(qbase + (size_t)r * QKVN + c * 4);
        v.x *= qscale; v.y *= qscale; v.z *= qscale; v.w *= qscale;
        __nv_bfloat16 h0 = __float2bfloat16(v.x), h1 = __float2bfloat16(v.y);
        __nv_bfloat16 h2 = __float2bfloat16(v.z), h3 = __float2bfloat16(v.w);
        __nv_bfloat16 l0 = __float2bfloat16(v.x - __bfloat162float(h0));
        __nv_bfloat16 l1 = __float2bfloat16(v.y - __bfloat162float(h1));
        __nv_bfloat16 l2 = __float2bfloat16(v.z - __bfloat162float(h2));
        __nv_bfloat16 l3 = __float2bfloat16(v.w - __bfloat162float(h3));
        __nv_bfloat162* dh = (__nv_bfloat162*)(sm + QH_OFF + r * ASTR + c * 8);
        __nv_bfloat162* dl = (__nv_bfloat162*)(sm + QL_OFF + r * ASTR + c * 8);
        dh[0] = __nv_bfloat162(h0, h1); dh[1] = __nv_bfloat162(h2, h3);
        dl[0] = __nv_bfloat162(l0, l1); dl[1] = __nv_bfloat162(l2, l3);
    }

    float acc_o[16][4];
    #pragma unroll
    for (int f = 0; f < 16; f++)
        #pragma unroll
        for (int q = 0; q < 4; q++) acc_o[f][q] = 0.f;
    float m0 = -INFINITY, m1 = -INFINITY, l0 = 0.f, l1 = 0.f;

    const float* kb0 = g_qkv + (size_t)(b * SEQ) * QKVN + NH * HD + kvh * HD;
    const float* vb0 = kb0 + NKV * HD;
    const int qrow0 = qt * 128 + 16 * wid + (lane >> 2);   // this thread's row r

    // ldmatrix offsets
    const uint32_t a_off = (uint32_t)(16 * wid + (lane & 15)) * ASTR + (lane >> 4) * 16;
    const uint32_t kb_off = (uint32_t)((lane & 7) + ((lane >> 4) & 1) * 8) * ASTR
                          + ((lane >> 3) & 1) * 16;
    const uint32_t v_off = (uint32_t)(lane & 15) * ASTR + (lane >> 4) * 16;

    const int nkt = 2 * qt + 2;
    for (int kt = 0; kt < nkt; kt++) {
        __syncthreads();   // previous iteration done with K/V smem (also Q store)
        // ---- load K,V tile (64 x 128 each), hi/lo split ----
        for (int i = tid; i < 64 * 32 * 2; i += 256) {
            int ten = i >> 11;                 // 0:K 1:V
            int r = (i >> 5) & 63, c = i & 31;
            const float* src = (ten ? vb0 : kb0) + (size_t)(kt * 64 + r) * QKVN + c * 4;
            float4 v = *(const float4*)src;
            __nv_bfloat16 h0 = __float2bfloat16(v.x), h1 = __float2bfloat16(v.y);
            __nv_bfloat16 h2 = __float2bfloat16(v.z), h3 = __float2bfloat16(v.w);
            __nv_bfloat16 e0 = __float2bfloat16(v.x - __bfloat162float(h0));
            __nv_bfloat16 e1 = __float2bfloat16(v.y - __bfloat162float(h1));
            __nv_bfloat16 e2 = __float2bfloat16(v.z - __bfloat162float(h2));
            __nv_bfloat16 e3 = __float2bfloat16(v.w - __bfloat162float(h3));
            int hof = (ten ? VH_OFF : KH_OFF) + r * ASTR + c * 8;
            int lof = (ten ? VL_OFF : KL_OFF) + r * ASTR + c * 8;
            __nv_bfloat162* dh = (__nv_bfloat162*)(sm + hof);
            __nv_bfloat162* dl = (__nv_bfloat162*)(sm + lof);
            dh[0] = __nv_bfloat162(h0, h1); dh[1] = __nv_bfloat162(h2, h3);
            dl[0] = __nv_bfloat162(e0, e1); dl[1] = __nv_bfloat162(e2, e3);
        }
        __syncthreads();

        // ---- S = Q K^T (3-term split), warp tile 16x64 ----
        float s[8][4];
        #pragma unroll
        for (int j = 0; j < 8; j++)
            #pragma unroll
            for (int q = 0; q < 4; q++) s[j][q] = 0.f;

        #pragma unroll
        for (int kk = 0; kk < 8; kk++) {
            uint32_t ah[4], al[4];
            ldsm4(ah, sb + QH_OFF + a_off + kk * 32);
            ldsm4(al, sb + QL_OFF + a_off + kk * 32);
            uint32_t bh[4][4], bl[4][4];
            #pragma unroll
            for (int p = 0; p < 4; p++) {
                ldsm4(bh[p], sb + KH_OFF + kb_off + (uint32_t)p * (16 * ASTR) + kk * 32);
                ldsm4(bl[p], sb + KL_OFF + kb_off + (uint32_t)p * (16 * ASTR) + kk * 32);
            }
            #pragma unroll
            for (int p = 0; p < 4; p++)
                #pragma unroll
                for (int q = 0; q < 2; q++) {
                    int j = p * 2 + q;
                    mma16816(s[j], ah, bh[p][q * 2], bh[p][q * 2 + 1]);
                    mma16816(s[j], al, bh[p][q * 2], bh[p][q * 2 + 1]);
                    mma16816(s[j], ah, bl[p][q * 2], bl[p][q * 2 + 1]);
                }
        }

        // ---- causal mask (diagonal region) + row max ----
        if (kt >= 2 * qt) {
            #pragma unroll
            for (int j = 0; j < 8; j++) {
                int c0 = kt * 64 + 8 * j + 2 * (lane & 3);
                if (c0     > qrow0)     s[j][0] = -INFINITY;
                if (c0 + 1 > qrow0)     s[j][1] = -INFINITY;
                if (c0     > qrow0 + 8) s[j][2] = -INFINITY;
                if (c0 + 1 > qrow0 + 8) s[j][3] = -INFINITY;
            }
        }
        float tm0 = -INFINITY, tm1 = -INFINITY;
        #pragma unroll
        for (int j = 0; j < 8; j++) {
            tm0 = fmaxf(tm0, fmaxf(s[j][0], s[j][1]));
            tm1 = fmaxf(tm1, fmaxf(s[j][2], s[j][3]));
        }
        tm0 = fmaxf(tm0, __shfl_xor_sync(0xffffffffu, tm0, 1));
        tm0 = fmaxf(tm0, __shfl_xor_sync(0xffffffffu, tm0, 2));
        tm1 = fmaxf(tm1, __shfl_xor_sync(0xffffffffu, tm1, 1));
        tm1 = fmaxf(tm1, __shfl_xor_sync(0xffffffffu, tm1, 2));
        float mn0 = fmaxf(m0, tm0), mn1 = fmaxf(m1, tm1);
        float sc0 = exp2f(m0 - mn0), sc1 = exp2f(m1 - mn1);

        // ---- P = exp2(S - m), pack hi/lo A-fragments, partial row sums ----
        uint32_t ap[4][4], apl[4][4];
        float ps0 = 0.f, ps1 = 0.f;
        #pragma unroll
        for (int t = 0; t < 4; t++) {
            #pragma unroll
            for (int q = 0; q < 2; q++) {
                int j = t * 2 + q;
                float p0 = exp2f(s[j][0] - mn0);
                float p1 = exp2f(s[j][1] - mn0);
                float p2 = exp2f(s[j][2] - mn1);
                float p3 = exp2f(s[j][3] - mn1);
                ps0 += p0 + p1; ps1 += p2 + p3;
                uint32_t hh0 = packbf2(p0, p1), hh1 = packbf2(p2, p3);
                __nv_bfloat162 hv0 = *(__nv_bfloat162*)&hh0;
                __nv_bfloat162 hv1 = *(__nv_bfloat162*)&hh1;
                uint32_t ll0 = packbf2(p0 - __bfloat162float(hv0.x),
                                       p1 - __bfloat162float(hv0.y));
                uint32_t ll1 = packbf2(p2 - __bfloat162float(hv1.x),
                                       p3 - __bfloat162float(hv1.y));
                ap[t][q * 2]      = hh0;
                ap[t][q * 2 + 1]  = hh1;
                apl[t][q * 2]     = ll0;
                apl[t][q * 2 + 1] = ll1;
            }
        }
        ps0 += __shfl_xor_sync(0xffffffffu, ps0, 1);
        ps0 += __shfl_xor_sync(0xffffffffu, ps0, 2);
        ps1 += __shfl_xor_sync(0xffffffffu, ps1, 1);
        ps1 += __shfl_xor_sync(0xffffffffu, ps1, 2);
        l0 = l0 * sc0 + ps0;
        l1 = l1 * sc1 + ps1;
        m0 = mn0; m1 = mn1;

        // ---- rescale O ----
        #pragma unroll
        for (int f = 0; f < 16; f++) {
            acc_o[f][0] *= sc0; acc_o[f][1] *= sc0;
            acc_o[f][2] *= sc1; acc_o[f][3] *= sc1;
        }

        // ---- O += P V (3-term split) ----
        #pragma unroll
        for (int t = 0; t < 4; t++) {
            #pragma unroll
            for (int db = 0; db < 8; db++) {
                uint32_t bv[4];
                ldsm4t(bv, sb + VH_OFF + v_off + (uint32_t)t * (16 * ASTR) + db * 32);
                mma16816(acc_o[db * 2],     ap[t],  bv[0], bv[1]);
                mma16816(acc_o[db * 2 + 1], ap[t],  bv[2], bv[3]);
                mma16816(acc_o[db * 2],     apl[t], bv[0], bv[1]);
                mma16816(acc_o[db * 2 + 1], apl[t], bv[2], bv[3]);
                ldsm4t(bv, sb + VL_OFF + v_off + (uint32_t)t * (16 * ASTR) + db * 32);
                mma16816(acc_o[db * 2],     ap[t],  bv[0], bv[1]);
                mma16816(acc_o[db * 2 + 1], ap[t],  bv[2], bv[3]);
            }
        }
    }

    // ---- epilogue ----
    float inv0 = 1.f / l0, inv1 = 1.f / l1;
    const size_t row0 = (size_t)(b * SEQ + qrow0);
    const int col0 = h * HD + 2 * (lane & 3);
    #pragma unroll
    for (int f = 0; f < 16; f++) {
        *(float2*)(g_ctx + row0 * HID + col0 + 8 * f) =
            make_float2(acc_o[f][0] * inv0, acc_o[f][1] * inv0);
        *(float2*)(g_ctx + (row0 + 8) * HID + col0 + 8 * f) =
            make_float2(acc_o[f][2] * inv1, acc_o[f][3] * inv1);
    }
}

// ---------------------------------------------------------------------------
extern "C" void kernel_launch(void* const* d_in, const int* in_sizes, int n_in,
                              void* d_out, int out_size) {
    const float* hidden = (const float*)d_in[0];
    const float* cosb   = (const float*)d_in[1];
    const float* sinb   = (const float*)d_in[2];
    const float* wqkv   = (const float*)d_in[3];
    const float* wo     = (const float*)d_in[4];
    const float* kc_in  = (const float*)d_in[5];
    const float* vc_in  = (const float*)d_in[6];
    const int*   slots  = (const int*)d_in[7];
    float* out = (float*)d_out;

    const size_t out_elems   = (size_t)TT * HID;
    const size_t cache_elems = (size_t)NSLOTS * NKV * HD;
    float* okc = nullptr;
    float* ovc = nullptr;
    if ((size_t)out_size >= out_elems + 2 * cache_elems) {
        okc = out + out_elems;
        ovc = okc + cache_elems;
    }

    cudaFuncSetAttribute(gemm_bf16, cudaFuncAttributeMaxDynamicSharedMemorySize, GEMM_SMEM);
    cudaFuncSetAttribute(attn_mma, cudaFuncAttributeMaxDynamicSharedMemorySize, ATT_SMEM);

    if (okc) {
        int n4 = (int)(cache_elems / 4);
        copy_caches<<<(n4 + 255) / 256, 256>>>((const float4*)kc_in, (const float4*)vc_in,
                                               (float4*)okc, (float4*)ovc, n4);
    }

    // expand operands for QKV GEMM
    expand3<<<(TT   * (KTOT / 4) + 255) / 256, 256>>>(hidden, TT,   0);
    expand3<<<(QKVN * (KTOT / 4) + 255) / 256, 256>>>(wqkv,   QKVN, 1);

    // 1) QKV projection -> g_qkv
    gemm_bf16<<<dim3(QKVN / BN, TT / BM), 256, GEMM_SMEM>>>(0, nullptr);

    // 2) RoPE + k scatter
    {
        int n = TT * (NH + NKV) * ROT;
        rope_scatter<<<(n + 255) / 256, 256>>>(cosb, sinb, slots, okc);
    }
    // 3) v scatter
    if (ovc) {
        v_scatter<<<(TT * NKV * HD + 255) / 256, 256>>>(slots, ovc);
    }

    // 4) attention -> g_ctx (tensor cores)
    attn_mma<<<dim3(SEQ / 128, NH, BATCH), 256, ATT_SMEM>>>();

    // 5) expand ctx + w_o, then O projection -> d_out
    expand3<<<(TT  * (KTOT / 4) + 255) / 256, 256>>>(nullptr, TT,  3);
    expand3<<<(HID * (KTOT / 4) + 255) / 256, 256>>>(wo,      HID, 2);
    gemm_bf16<<<dim3(HID / BN, TT / BM), 256, GEMM_SMEM>>>(1, out);
}